// round 7
// baseline (speedup 1.0000x reference)
#include <cuda_runtime.h>

#define NN 50000
#define EE 1600000
#define GG 128
#define HC1 128      // 4 heads * 32 ch
#define C2 64
#define EPS_ 1e-5f
#define NBLK 196     // ceil(50000/256)
#define ECAP (EE + NN)

// ---------------- scratch (static device memory; no allocs) ----------------
__device__ __align__(16) float g_xl1[NN * HC1];
__device__ __align__(16) float g_xr1[NN * HC1];
__device__ __align__(16) float g_h1 [NN * HC1];
__device__ __align__(16) float g_xl2[NN * C2];
__device__ __align__(16) float g_xr2[NN * C2];
__device__ __align__(16) float g_h2 [NN * C2];
__device__ int   g_deg[NN];
__device__ int   g_off[NN + 1];
__device__ int   g_cur[NN];
__device__ int   g_csr[ECAP];
__device__ int   g_part[NBLK];
__device__ int   g_top[NBLK];
__device__ float g_stats1[2 * HC1];
__device__ float g_stats2[2 * C2];
__device__ __align__(16) float g_w2eff[HC1 * HC1];  // BN1-folded [W2l | W2r]
__device__ float g_b2eff[HC1];
__device__ float g_bn2sc[C2];
__device__ float g_bn2sh[C2];

// ---------------- prep: deg=1 (self loop), zero stat accumulators ----------
__global__ void prep_kernel() {
    int i = blockIdx.x * blockDim.x + threadIdx.x;
    if (i < NN) g_deg[i] = 1;
    if (i < 2 * HC1) g_stats1[i] = 0.f;
    if (i < 2 * C2)  g_stats2[i] = 0.f;
}

// ---------------- in-degree histogram --------------------------------------
__global__ void hist_kernel(const int* __restrict__ ei) {
    int e = blockIdx.x * blockDim.x + threadIdx.x;
    if (e < EE) {
        int d = ei[EE + e];
        if ((unsigned)d >= NN) d = 0;   // defensive clamp
        atomicAdd(&g_deg[d], 1);
    }
}

// ---------------- 3-phase exclusive scan of degrees (256-thread blocks) ----
__global__ void scan_part_kernel() {
    __shared__ int s[256];
    int t = threadIdx.x;
    int i = blockIdx.x * 256 + t;
    int v = (i < NN) ? g_deg[i] : 0;
    s[t] = v;
    __syncthreads();
    for (int o = 128; o > 0; o >>= 1) {
        if (t < o) s[t] += s[t + o];
        __syncthreads();
    }
    if (t == 0) g_part[blockIdx.x] = s[0];
}

__global__ void scan_top_kernel() {
    __shared__ int s[256];
    int t = threadIdx.x;
    int v = (t < NBLK) ? g_part[t] : 0;
    s[t] = v;
    __syncthreads();
    for (int o = 1; o < 256; o <<= 1) {
        int tv = (t >= o) ? s[t - o] : 0;
        __syncthreads();
        s[t] += tv;
        __syncthreads();
    }
    if (t < NBLK) g_top[t] = s[t] - v;      // exclusive prefix
    if (t == 255) g_off[NN] = s[255];       // total
}

__global__ void scan_add_kernel() {
    __shared__ int s[256];
    int t = threadIdx.x;
    int i = blockIdx.x * 256 + t;
    int v = (i < NN) ? g_deg[i] : 0;
    s[t] = v;
    __syncthreads();
    for (int o = 1; o < 256; o <<= 1) {
        int tv = (t >= o) ? s[t - o] : 0;
        __syncthreads();
        s[t] += tv;
        __syncthreads();
    }
    int e = g_top[blockIdx.x] + s[t] - v;
    if (i < NN) { g_off[i] = e; g_cur[i] = e; }
}

// ---------------- CSR scatter (edges + self loops) --------------------------
__global__ void scatter_kernel(const int* __restrict__ ei) {
    int i = blockIdx.x * blockDim.x + threadIdx.x;
    if (i < EE) {
        int sidx = ei[i];
        int d = ei[EE + i];
        if ((unsigned)sidx >= NN) sidx = 0;
        if ((unsigned)d >= NN) d = 0;
        int pos = atomicAdd(&g_cur[d], 1);
        if ((unsigned)pos < ECAP) g_csr[pos] = sidx;
    } else if (i < ECAP) {
        int v = i - EE;
        int pos = atomicAdd(&g_cur[v], 1);
        if ((unsigned)pos < ECAP) g_csr[pos] = v;
    }
}

// ---------------- GEMM1: x[50000,64] @ [W1l|W1r][64,256] -> xl1,xr1 --------
__global__ void gemm1_kernel(const float* __restrict__ x,
                             const float* __restrict__ W1l, const float* __restrict__ b1l,
                             const float* __restrict__ W1r, const float* __restrict__ b1r) {
    __shared__ float As[64 * 32];
    __shared__ float Bs[32 * 256];
    int t = threadIdx.x;
    int tx = t & 31;        // cols tx*8 .. tx*8+7 (of 256)
    int ty = t >> 5;        // rows ty*8 .. ty*8+7 (of 64)
    int row0 = blockIdx.x * 64;

    float acc[8][8];
#pragma unroll
    for (int i = 0; i < 8; i++)
#pragma unroll
        for (int j = 0; j < 8; j++) acc[i][j] = 0.f;

    for (int kb = 0; kb < 64; kb += 32) {
#pragma unroll
        for (int u = 0; u < 8; u++) {
            int idx = t + u * 256;
            int r = idx >> 5, k = idx & 31;
            int grow = row0 + r;
            As[idx] = (grow < NN) ? x[grow * 64 + kb + k] : 0.f;
        }
#pragma unroll
        for (int u = 0; u < 32; u++) {
            int idx = t + u * 256;
            int k = idx >> 8, j = idx & 255;
            Bs[idx] = (j < 128) ? W1l[(kb + k) * 128 + j]
                                : W1r[(kb + k) * 128 + (j - 128)];
        }
        __syncthreads();
#pragma unroll
        for (int k = 0; k < 32; k++) {
            float a[8];
#pragma unroll
            for (int i = 0; i < 8; i++) a[i] = As[(ty * 8 + i) * 32 + k];
            float b[8];
#pragma unroll
            for (int j = 0; j < 8; j++) b[j] = Bs[k * 256 + tx * 8 + j];
#pragma unroll
            for (int i = 0; i < 8; i++)
#pragma unroll
                for (int j = 0; j < 8; j++) acc[i][j] += a[i] * b[j];
        }
        __syncthreads();
    }

    int j0 = tx * 8;
#pragma unroll
    for (int i = 0; i < 8; i++) {
        int grow = row0 + ty * 8 + i;
        if (grow < NN) {
            if (j0 < 128) {
#pragma unroll
                for (int j = 0; j < 8; j++)
                    g_xl1[grow * 128 + j0 + j] = acc[i][j] + b1l[j0 + j];
            } else {
#pragma unroll
                for (int j = 0; j < 8; j++)
                    g_xr1[grow * 128 + (j0 - 128) + j] = acc[i][j] + b1r[(j0 - 128) + j];
            }
        }
    }
}

// ---------------- Layer-1 aggregation: one warp per dst node ----------------
__global__ void agg1_kernel(const float* __restrict__ att1,
                            const float* __restrict__ bias1) {
    __shared__ float sbuf[8][HC1];
    __shared__ float qbuf[8][HC1];
    int t = threadIdx.x;
    int warp = t >> 5, lane = t & 31;
    int node = blockIdx.x * 8 + warp;

    float o0 = 0.f, o1 = 0.f, o2 = 0.f, o3 = 0.f;
    if (node < NN) {
        int base = g_off[node];
        int end  = g_off[node + 1];
        if (base < 0) base = 0; if (base > ECAP) base = ECAP;
        if (end < base) end = base; if (end > ECAP) end = ECAP;
        int deg = end - base;

        float4 xr = *(const float4*)&g_xr1[node * 128 + lane * 4];
        float a0 = att1[lane * 4], a1 = att1[lane * 4 + 1];
        float a2 = att1[lane * 4 + 2], a3 = att1[lane * 4 + 3];
        float4 acc = make_float4(0.f, 0.f, 0.f, 0.f);
        float denom = 0.f;

        for (int ch = 0; ch < deg; ch += 32) {
            int idx = ch + lane;
            int sv = 0;
            if (idx < deg) {
                sv = g_csr[base + idx];
                if ((unsigned)sv >= NN) sv = 0;
            }
            int cnt = min(32, deg - ch);
            for (int j = 0; j < cnt; j++) {
                int s = __shfl_sync(0xffffffffu, sv, j);
                float4 v = *(const float4*)&g_xl1[s * 128 + lane * 4];
                float m0 = v.x + xr.x; m0 = fmaxf(m0, 0.2f * m0);
                float m1 = v.y + xr.y; m1 = fmaxf(m1, 0.2f * m1);
                float m2 = v.z + xr.z; m2 = fmaxf(m2, 0.2f * m2);
                float m3 = v.w + xr.w; m3 = fmaxf(m3, 0.2f * m3);
                float p = m0 * a0 + m1 * a1 + m2 * a2 + m3 * a3;
                // reduce within 8-lane group (one head per 8 lanes)
                p += __shfl_xor_sync(0xffffffffu, p, 1);
                p += __shfl_xor_sync(0xffffffffu, p, 2);
                p += __shfl_xor_sync(0xffffffffu, p, 4);
                float w = __expf(p);    // logits tiny: no max-subtraction needed
                denom += w;
                acc.x += w * v.x; acc.y += w * v.y;
                acc.z += w * v.z; acc.w += w * v.w;
            }
        }
        float inv = 1.f / denom;        // self loop guarantees denom > 0
        int c0 = lane * 4;
        o0 = fmaxf(acc.x * inv + bias1[c0],     0.f);
        o1 = fmaxf(acc.y * inv + bias1[c0 + 1], 0.f);
        o2 = fmaxf(acc.z * inv + bias1[c0 + 2], 0.f);
        o3 = fmaxf(acc.w * inv + bias1[c0 + 3], 0.f);
        *(float4*)&g_h1[node * 128 + c0] = make_float4(o0, o1, o2, o3);
    }
    int c0 = lane * 4;
    sbuf[warp][c0] = o0; sbuf[warp][c0 + 1] = o1;
    sbuf[warp][c0 + 2] = o2; sbuf[warp][c0 + 3] = o3;
    qbuf[warp][c0] = o0 * o0; qbuf[warp][c0 + 1] = o1 * o1;
    qbuf[warp][c0 + 2] = o2 * o2; qbuf[warp][c0 + 3] = o3 * o3;
    __syncthreads();
    if (t < HC1) {
        float s = 0.f, q = 0.f;
#pragma unroll
        for (int w = 0; w < 8; w++) { s += sbuf[w][t]; q += qbuf[w][t]; }
        atomicAdd(&g_stats1[t], s);
        atomicAdd(&g_stats1[HC1 + t], q);
    }
}

// ---------------- BN1 finalize + fold into layer-2 weights ------------------
__global__ void bn1_w2eff_kernel(const float* __restrict__ bn1g, const float* __restrict__ bn1b,
                                 const float* __restrict__ W2l, const float* __restrict__ b2l,
                                 const float* __restrict__ W2r, const float* __restrict__ b2r) {
    __shared__ float sc[HC1], sh[HC1];
    int t = threadIdx.x;   // 256 threads
    if (t < HC1) {
        float mu  = g_stats1[t] * (1.f / NN);
        float var = g_stats1[HC1 + t] * (1.f / NN) - mu * mu;
        float s = bn1g[t] * rsqrtf(var + EPS_);
        sc[t] = s;
        sh[t] = bn1b[t] - mu * s;
    }
    __syncthreads();
    for (int idx = t; idx < HC1 * HC1; idx += 256) {
        int j = idx >> 7, c = idx & 127;
        float w = (c < 64) ? W2l[j * 64 + c] : W2r[j * 64 + (c - 64)];
        g_w2eff[idx] = w * sc[j];
    }
    if (t < HC1) {
        int c = t & 63;
        bool left = (t < 64);
        float s2 = 0.f;
        for (int j = 0; j < HC1; j++) {
            float w = left ? W2l[j * 64 + c] : W2r[j * 64 + c];
            s2 += sh[j] * w;
        }
        g_b2eff[t] = (left ? b2l[c] : b2r[c]) + s2;
    }
}

// ---------------- GEMM2: h1[50000,128] @ w2eff[128,128] -> xl2,xr2 ----------
__global__ void gemm2_kernel() {
    __shared__ float As[64 * 32];
    __shared__ float Bs[32 * 128];
    int t = threadIdx.x;
    int tx = t & 15;        // cols tx*8 of 128
    int ty = t >> 4;        // rows ty*4 of 64
    int row0 = blockIdx.x * 64;

    float acc[4][8];
#pragma unroll
    for (int i = 0; i < 4; i++)
#pragma unroll
        for (int j = 0; j < 8; j++) acc[i][j] = 0.f;

    for (int kb = 0; kb < 128; kb += 32) {
#pragma unroll
        for (int u = 0; u < 8; u++) {
            int idx = t + u * 256;
            int r = idx >> 5, k = idx & 31;
            int grow = row0 + r;
            As[idx] = (grow < NN) ? g_h1[grow * 128 + kb + k] : 0.f;
        }
#pragma unroll
        for (int u = 0; u < 16; u++) {
            int idx = t + u * 256;
            int k = idx >> 7, j = idx & 127;
            Bs[idx] = g_w2eff[(kb + k) * 128 + j];
        }
        __syncthreads();
#pragma unroll
        for (int k = 0; k < 32; k++) {
            float a[4];
#pragma unroll
            for (int i = 0; i < 4; i++) a[i] = As[(ty * 4 + i) * 32 + k];
            float b[8];
#pragma unroll
            for (int j = 0; j < 8; j++) b[j] = Bs[k * 128 + tx * 8 + j];
#pragma unroll
            for (int i = 0; i < 4; i++)
#pragma unroll
                for (int j = 0; j < 8; j++) acc[i][j] += a[i] * b[j];
        }
        __syncthreads();
    }

    int j0 = tx * 8;
#pragma unroll
    for (int i = 0; i < 4; i++) {
        int grow = row0 + ty * 4 + i;
        if (grow < NN) {
            if (j0 < 64) {
#pragma unroll
                for (int j = 0; j < 8; j++)
                    g_xl2[grow * 64 + j0 + j] = acc[i][j] + g_b2eff[j0 + j];
            } else {
#pragma unroll
                for (int j = 0; j < 8; j++)
                    g_xr2[grow * 64 + (j0 - 64) + j] = acc[i][j] + g_b2eff[j0 + j];
            }
        }
    }
}

// ---------------- Layer-2 aggregation (1 head, 64 ch) -----------------------
__global__ void agg2_kernel(const float* __restrict__ att2,
                            const float* __restrict__ bias2) {
    __shared__ float sbuf[8][C2];
    __shared__ float qbuf[8][C2];
    int t = threadIdx.x;
    int warp = t >> 5, lane = t & 31;
    int node = blockIdx.x * 8 + warp;

    float o0 = 0.f, o1 = 0.f;
    if (node < NN) {
        int base = g_off[node];
        int end  = g_off[node + 1];
        if (base < 0) base = 0; if (base > ECAP) base = ECAP;
        if (end < base) end = base; if (end > ECAP) end = ECAP;
        int deg = end - base;

        float2 xr = *(const float2*)&g_xr2[node * 64 + lane * 2];
        float a0 = att2[lane * 2], a1 = att2[lane * 2 + 1];
        float2 acc = make_float2(0.f, 0.f);
        float denom = 0.f;

        for (int ch = 0; ch < deg; ch += 32) {
            int idx = ch + lane;
            int sv = 0;
            if (idx < deg) {
                sv = g_csr[base + idx];
                if ((unsigned)sv >= NN) sv = 0;
            }
            int cnt = min(32, deg - ch);
            for (int j = 0; j < cnt; j++) {
                int s = __shfl_sync(0xffffffffu, sv, j);
                float2 v = *(const float2*)&g_xl2[s * 64 + lane * 2];
                float m0 = v.x + xr.x; m0 = fmaxf(m0, 0.2f * m0);
                float m1 = v.y + xr.y; m1 = fmaxf(m1, 0.2f * m1);
                float p = m0 * a0 + m1 * a1;
                p += __shfl_xor_sync(0xffffffffu, p, 16);
                p += __shfl_xor_sync(0xffffffffu, p, 8);
                p += __shfl_xor_sync(0xffffffffu, p, 4);
                p += __shfl_xor_sync(0xffffffffu, p, 2);
                p += __shfl_xor_sync(0xffffffffu, p, 1);
                float w = __expf(p);
                denom += w;
                acc.x += w * v.x;
                acc.y += w * v.y;
            }
        }
        float inv = 1.f / denom;
        int c0 = lane * 2;
        o0 = fmaxf(acc.x * inv + bias2[c0],     0.f);
        o1 = fmaxf(acc.y * inv + bias2[c0 + 1], 0.f);
        *(float2*)&g_h2[node * 64 + c0] = make_float2(o0, o1);
    }
    int c0 = lane * 2;
    sbuf[warp][c0] = o0; sbuf[warp][c0 + 1] = o1;
    qbuf[warp][c0] = o0 * o0; qbuf[warp][c0 + 1] = o1 * o1;
    __syncthreads();
    if (t < C2) {
        float s = 0.f, q = 0.f;
#pragma unroll
        for (int w = 0; w < 8; w++) { s += sbuf[w][t]; q += qbuf[w][t]; }
        atomicAdd(&g_stats2[t], s);
        atomicAdd(&g_stats2[C2 + t], q);
    }
}

// ---------------- BN2 finalize ----------------------------------------------
__global__ void bn2_kernel(const float* __restrict__ g2, const float* __restrict__ b2) {
    int c = threadIdx.x;
    if (c < C2) {
        float mu  = g_stats2[c] * (1.f / NN);
        float var = g_stats2[C2 + c] * (1.f / NN) - mu * mu;
        float s = g2[c] * rsqrtf(var + EPS_);
        g_bn2sc[c] = s;
        g_bn2sh[c] = b2[c] - mu * s;
    }
}

// ---------------- pooling (sum/mean/max) + final linear ---------------------
__device__ __forceinline__ int lbound_i(const int* a, int n, int key) {
    int lo = 0, hi = n;
    while (lo < hi) {
        int m = (lo + hi) >> 1;
        if (a[m] < key) lo = m + 1; else hi = m;
    }
    return lo;
}

__global__ void pool_kernel(const int* __restrict__ batch,
                            const float* __restrict__ linw,
                            const float* __restrict__ linb,
                            float* __restrict__ out) {
    __shared__ float red[4][C2];
    __shared__ float rmx[4][C2];
    __shared__ float sfeat[3 * C2];
    int g = blockIdx.x;
    int t = threadIdx.x;
    int c = t & 63;
    int r = t >> 6;   // 0..3

    int s0 = lbound_i(batch, NN, g);
    int s1 = lbound_i(batch, NN, g + 1);

    float sc = g_bn2sc[c], sh = g_bn2sh[c];
    float sum = 0.f, mx = -3.402823466e38f;
    for (int v = s0 + r; v < s1; v += 4) {
        float y = g_h2[v * 64 + c] * sc + sh;
        sum += y;
        mx = fmaxf(mx, y);
    }
    red[r][c] = sum;
    rmx[r][c] = mx;
    __syncthreads();
    if (r == 0) {
        float tot = red[0][c] + red[1][c] + red[2][c] + red[3][c];
        int cnt = s1 - s0;
        sfeat[c] = tot;
        sfeat[64 + c] = tot / (float)max(cnt, 1);
        sfeat[128 + c] = fmaxf(fmaxf(rmx[0][c], rmx[1][c]),
                               fmaxf(rmx[2][c], rmx[3][c]));
    }
    __syncthreads();
    if (t < 64) {
        int o = t >> 5;     // output 0 or 1
        int l = t & 31;
        float p = 0.f;
        for (int f = l; f < 192; f += 32) p += sfeat[f] * linw[f * 2 + o];
        p += __shfl_xor_sync(0xffffffffu, p, 16);
        p += __shfl_xor_sync(0xffffffffu, p, 8);
        p += __shfl_xor_sync(0xffffffffu, p, 4);
        p += __shfl_xor_sync(0xffffffffu, p, 2);
        p += __shfl_xor_sync(0xffffffffu, p, 1);
        if (l == 0) out[g * 2 + o] = p + linb[o];
    }
}

// ---------------- launch -----------------------------------------------------
extern "C" void kernel_launch(void* const* d_in, const int* in_sizes, int n_in,
                              void* d_out, int out_size) {
    const float* x     = (const float*)d_in[0];
    const int*   ei    = (const int*)d_in[1];    // int32! (JAX x64 disabled)
    const int*   batch = (const int*)d_in[2];    // int32!
    const float* W1l  = (const float*)d_in[3];
    const float* b1l  = (const float*)d_in[4];
    const float* W1r  = (const float*)d_in[5];
    const float* b1r  = (const float*)d_in[6];
    const float* att1 = (const float*)d_in[7];
    const float* bias1= (const float*)d_in[8];
    const float* W2l  = (const float*)d_in[9];
    const float* b2l  = (const float*)d_in[10];
    const float* W2r  = (const float*)d_in[11];
    const float* b2r  = (const float*)d_in[12];
    const float* att2 = (const float*)d_in[13];
    const float* bias2= (const float*)d_in[14];
    const float* bn1g = (const float*)d_in[15];
    const float* bn1b = (const float*)d_in[16];
    const float* bn2g = (const float*)d_in[17];
    const float* bn2b = (const float*)d_in[18];
    const float* linw = (const float*)d_in[19];
    const float* linb = (const float*)d_in[20];
    float* out = (float*)d_out;

    prep_kernel<<<(NN + 255) / 256, 256>>>();
    hist_kernel<<<(EE + 255) / 256, 256>>>(ei);
    scan_part_kernel<<<NBLK, 256>>>();
    scan_top_kernel<<<1, 256>>>();
    scan_add_kernel<<<NBLK, 256>>>();
    scatter_kernel<<<(ECAP + 255) / 256, 256>>>(ei);

    gemm1_kernel<<<(NN + 63) / 64, 256>>>(x, W1l, b1l, W1r, b1r);
    agg1_kernel<<<(NN + 7) / 8, 256>>>(att1, bias1);

    bn1_w2eff_kernel<<<1, 256>>>(bn1g, bn1b, W2l, b2l, W2r, b2r);
    gemm2_kernel<<<(NN + 63) / 64, 256>>>();
    agg2_kernel<<<(NN + 7) / 8, 256>>>(att2, bias2);

    bn2_kernel<<<1, 64>>>(bn2g, bn2b);
    pool_kernel<<<GG, 256>>>(batch, linw, linb, out);
}